// round 3
// baseline (speedup 1.0000x reference)
#include <cuda_runtime.h>

// Windowed 3D attention, fp32 baseline.
// Shapes: x[1,32,64,128,96], win 4x4x4 -> 4096 windows of s=64 tokens, heads=4, ch=24.
// One window per 256-thread CTA. 96KB dynamic smem (x tile + q/k/v, scores reuse x region).

#define Dd 32
#define Hh 64
#define Ww 128
#define Cc 96
#define NWIN 4096

__global__ __launch_bounds__(256, 2)
void win_attn_kernel(const float* __restrict__ x,
                     const float* __restrict__ wqkv,   // [96, 288] row-major
                     const float* __restrict__ wproj,  // [96, 96]  row-major
                     const float* __restrict__ bproj,  // [96]
                     float* __restrict__ out) {
    extern __shared__ float sm[];
    float* xs = sm;            // [64*96] x tile; reused later: scores[64*64] @0, kt @4096
    float* qs = sm + 6144;     // [64*96] q; per-head attn output written in place
    float* ks = sm + 12288;    // [64*96]
    float* vs = sm + 18432;    // [64*96]
    float* scores = sm;        // [64*64] (reuses xs)
    float* kt = sm + 4096;     // [24*65] padded K^T (reuses tail of xs region)

    const int tid  = threadIdx.x;
    const int lane = tid & 31;
    const int warp = tid >> 5;

    const int wid = blockIdx.x;
    const int l_i = wid & 31;
    const int m_i = (wid >> 5) & 15;
    const int n_i = wid >> 9;
    const int d0 = n_i * 4, h0 = m_i * 4, w0 = l_i * 4;

    // ---- load x tile: 64 rows x 96 floats (24 float4 per row) ----
    for (int idx = tid; idx < 64 * 24; idx += 256) {
        int r = idx / 24, c4 = idx % 24;
        int wd = r >> 4, wh = (r >> 2) & 3, ww = r & 3;
        long grow = ((long)(d0 + wd) * Hh + (h0 + wh)) * Ww + (w0 + ww);
        float4 v = reinterpret_cast<const float4*>(x + grow * Cc)[c4];
        reinterpret_cast<float4*>(xs + r * 96)[c4] = v;
    }
    __syncthreads();

    // ---- QKV GEMM: [64,96] @ [96,288] -> q/k/v smem ----
    {
        const int r0 = warp * 8;
        for (int cg = 0; cg < 3; cg++) {   // 0->q, 1->k, 2->v (96 cols each)
            float acc[8][3];
            #pragma unroll
            for (int a = 0; a < 8; a++) {
                acc[a][0] = 0.f; acc[a][1] = 0.f; acc[a][2] = 0.f;
            }
            const float* wp = wqkv + cg * 96 + lane;
            #pragma unroll 4
            for (int k = 0; k < 96; k++) {
                float wv0 = wp[k * 288];
                float wv1 = wp[k * 288 + 32];
                float wv2 = wp[k * 288 + 64];
                #pragma unroll
                for (int rr = 0; rr < 8; rr++) {
                    float xv = xs[(r0 + rr) * 96 + k];
                    acc[rr][0] += xv * wv0;
                    acc[rr][1] += xv * wv1;
                    acc[rr][2] += xv * wv2;
                }
            }
            float* dst = (cg == 0) ? qs : (cg == 1) ? ks : vs;
            #pragma unroll
            for (int rr = 0; rr < 8; rr++) {
                dst[(r0 + rr) * 96 + lane]      = acc[rr][0];
                dst[(r0 + rr) * 96 + 32 + lane] = acc[rr][1];
                dst[(r0 + rr) * 96 + 64 + lane] = acc[rr][2];
            }
        }
    }
    __syncthreads();   // xs reads done; xs region becomes scores/kt

    const float scale = rsqrtf(24.0f);

    // ---- per-head attention ----
    for (int h = 0; h < 4; h++) {
        const int hc = h * 24;
        // build padded K^T: kt[c][j], stride 65 (conflict-free both ways)
        for (int idx = tid; idx < 24 * 64; idx += 256) {
            int j = idx / 24, c = idx % 24;
            kt[c * 65 + j] = ks[j * 96 + hc + c];
        }
        __syncthreads();

        // scores = scale * q_h @ k_h^T : warp tile 8 rows x 64 cols
        {
            const int r0 = warp * 8;
            float acc[8][2];
            #pragma unroll
            for (int a = 0; a < 8; a++) { acc[a][0] = 0.f; acc[a][1] = 0.f; }
            #pragma unroll 4
            for (int c = 0; c < 24; c++) {
                float kv0 = kt[c * 65 + lane];
                float kv1 = kt[c * 65 + 32 + lane];
                #pragma unroll
                for (int rr = 0; rr < 8; rr++) {
                    float qv = qs[(r0 + rr) * 96 + hc + c];
                    acc[rr][0] += qv * kv0;
                    acc[rr][1] += qv * kv1;
                }
            }
            #pragma unroll
            for (int rr = 0; rr < 8; rr++) {
                scores[(r0 + rr) * 64 + lane]      = acc[rr][0] * scale;
                scores[(r0 + rr) * 64 + 32 + lane] = acc[rr][1] * scale;
            }
        }
        __syncthreads();

        // softmax over 64 cols: warp handles 8 rows, 2 elements per lane
        {
            const int r0 = warp * 8;
            #pragma unroll
            for (int rr = 0; rr < 8; rr++) {
                float a = scores[(r0 + rr) * 64 + lane];
                float b = scores[(r0 + rr) * 64 + 32 + lane];
                float m = fmaxf(a, b);
                #pragma unroll
                for (int off = 16; off; off >>= 1)
                    m = fmaxf(m, __shfl_xor_sync(0xFFFFFFFFu, m, off));
                float ea = __expf(a - m);
                float eb = __expf(b - m);
                float ssum = ea + eb;
                #pragma unroll
                for (int off = 16; off; off >>= 1)
                    ssum += __shfl_xor_sync(0xFFFFFFFFu, ssum, off);
                float inv = 1.0f / ssum;
                scores[(r0 + rr) * 64 + lane]      = ea * inv;
                scores[(r0 + rr) * 64 + 32 + lane] = eb * inv;
            }
        }
        __syncthreads();

        // out_h = P @ v_h, written in place over dead q_h columns.
        // No trailing sync needed: next iteration's kt-build touches neither
        // scores nor qs[h] cols, and its following __syncthreads orders the
        // next scores-write after every thread finishes here.
        {
            const int r0 = warp * 8;
            float acc[8];
            #pragma unroll
            for (int a = 0; a < 8; a++) acc[a] = 0.f;
            if (lane < 24) {
                #pragma unroll 4
                for (int j = 0; j < 64; j++) {
                    float vv = vs[j * 96 + hc + lane];
                    #pragma unroll
                    for (int rr = 0; rr < 8; rr++)
                        acc[rr] += scores[(r0 + rr) * 64 + j] * vv;
                }
                #pragma unroll
                for (int rr = 0; rr < 8; rr++)
                    qs[(r0 + rr) * 96 + hc + lane] = acc[rr];
            }
        }
        __syncthreads();
    }

    // ---- proj: [64,96] @ [96,96] + b, scatter back with window merge ----
    {
        const int r0 = warp * 8;
        float acc[8][3];
        #pragma unroll
        for (int a = 0; a < 8; a++) { acc[a][0] = 0.f; acc[a][1] = 0.f; acc[a][2] = 0.f; }
        #pragma unroll 4
        for (int k = 0; k < 96; k++) {
            float wv0 = wproj[k * 96 + lane];
            float wv1 = wproj[k * 96 + 32 + lane];
            float wv2 = wproj[k * 96 + 64 + lane];
            #pragma unroll
            for (int rr = 0; rr < 8; rr++) {
                float xv = qs[(r0 + rr) * 96 + k];
                acc[rr][0] += xv * wv0;
                acc[rr][1] += xv * wv1;
                acc[rr][2] += xv * wv2;
            }
        }
        float b0 = bproj[lane], b1 = bproj[32 + lane], b2 = bproj[64 + lane];
        #pragma unroll
        for (int rr = 0; rr < 8; rr++) {
            int r = r0 + rr;
            int wd = r >> 4, wh = (r >> 2) & 3, ww = r & 3;
            long grow = ((long)(d0 + wd) * Hh + (h0 + wh)) * Ww + (w0 + ww);
            float* op = out + grow * Cc;
            op[lane]      = acc[rr][0] + b0;
            op[32 + lane] = acc[rr][1] + b1;
            op[64 + lane] = acc[rr][2] + b2;
        }
    }
}

extern "C" void kernel_launch(void* const* d_in, const int* in_sizes, int n_in,
                              void* d_out, int out_size) {
    const float* x     = (const float*)d_in[0];
    const float* wqkv  = (const float*)d_in[1];
    const float* wproj = (const float*)d_in[2];
    const float* bproj = (const float*)d_in[3];
    float* out = (float*)d_out;

    // 96KB dynamic smem opt-in (attribute set is not a stream op; capture-safe)
    cudaFuncSetAttribute(win_attn_kernel,
                         cudaFuncAttributeMaxDynamicSharedMemorySize, 98304);
    win_attn_kernel<<<NWIN, 256, 98304>>>(x, wqkv, wproj, bproj, out);
}